// round 15
// baseline (speedup 1.0000x reference)
#include <cuda_runtime.h>
#include <math.h>

#define NB 16
#define NC 256
#define NH 32
#define NW 32
#define NK 81
#define NHW 1024
#define NCHW (NC*NHW)
#define NBHW (NB*NHW)
#define OUT_FLT (NB*NCHW)
#define FPAD 1600              // 40 rows x 40 floats
#define FPAD_C (NC*FPAD)

typedef unsigned long long u64;

__device__ __forceinline__ u64 ffma2(u64 a, u64 b, u64 c) {
    u64 d;
    asm("fma.rn.f32x2 %0, %1, %2, %3;" : "=l"(d) : "l"(a), "l"(b), "l"(c));
    return d;
}
__device__ __forceinline__ u64 addf2(u64 a, u64 b) {
    u64 d;
    asm("add.rn.f32x2 %0, %1, %2;" : "=l"(d) : "l"(a), "l"(b));
    return d;
}
__device__ __forceinline__ u64 mulf2(u64 a, u64 b) {
    u64 d;
    asm("mul.rn.f32x2 %0, %1, %2;" : "=l"(d) : "l"(a), "l"(b));
    return d;
}
__device__ __forceinline__ u64 shp(u64 a, u64 b) {   // (hi(a), lo(b))
    return (a >> 32) | (b << 32);
}
__device__ __forceinline__ float lo32(u64 a) { return __uint_as_float((unsigned)a); }
__device__ __forceinline__ float hi32(u64 a) { return __uint_as_float((unsigned)(a >> 32)); }

// ---------------- device scratch ----------------
__device__ float g_wlab[NK], g_wm[NK], g_wsw[NK];
__device__ float g_step, g_regw;
__device__ float g_flt[NB*NCHW];
__device__ float g_fg[NB*NCHW];
__device__ float g_mapped[NB*NK*NHW];
__device__ float g_maskw[NB*NK*NHW];
__device__ float g_anum[4*NBHW];
__device__ float g_featpad[NB*FPAD_C];   // 26.2 MB
__device__ float g_psrc[512], g_pfsq[512];
__device__ float g_losses[6];

// ---------------- prepad + init (merged) ----------------
__global__ void k_prepad(const float* __restrict__ feat,
                         const float* __restrict__ label_w,
                         const float* __restrict__ mask_w,
                         const float* __restrict__ spatial_w,
                         const float* __restrict__ logstep,
                         const float* __restrict__ freg) {
    if (blockIdx.x == 0) {
        int t = threadIdx.x;
        if (t < NK) {
            int k0 = t / 9, k1 = t % 9;
            float dist = sqrtf((float)((k0-4)*(k0-4) + (k1-4)*(k1-4)));
            float lab = 0.f, mk = 0.f, sw = 0.f;
            #pragma unroll
            for (int d = 0; d < 10; d++) {
                float diff = dist * 2.0f - (float)d;
                float bv;
                if (d < 9) bv = fmaxf(0.f, 1.f - fabsf(diff));
                else       bv = fminf(fmaxf(1.f + diff, 0.f), 1.f);
                lab += bv * label_w[d];
                mk  += bv * mask_w[d];
                sw  += bv * spatial_w[d];
            }
            g_wlab[t] = lab;
            g_wm[t]   = 1.f / (1.f + expf(-mk));
            g_wsw[t]  = sw;
        }
        if (t == 96) g_step = expf(logstep[0]);
        if (t == 97) {
            float fr = freg[0];
            g_regw = fmaxf(fr * fr, 1e-10f) / ((float)NC * (float)NC);
        }
    }
    int bc = blockIdx.x;
    const float* src = feat + bc * NHW;
    float4* dst = (float4*)(g_featpad + bc * FPAD);
    for (int t = threadIdx.x; t < 400; t += 128) {
        int py = t / 10, e = t - py * 10;
        float4 v = make_float4(0.f, 0.f, 0.f, 0.f);
        if (py >= 4 && py < 36 && e >= 1 && e <= 8)
            v = *(const float4*)(src + (py - 4) * NW + e * 4 - 4);
        dst[t] = v;
    }
}

#define CORR_TAPS(flo, fhi, p0,p1,p2,p3,p4,p5, s0,s1,s2,s3,s4, A)  \
    A[0][0]=ffma2(flo,p0,A[0][0]); A[0][1]=ffma2(flo,s0,A[0][1]);  \
    A[0][2]=ffma2(flo,p1,A[0][2]); A[0][3]=ffma2(flo,s1,A[0][3]);  \
    A[0][4]=ffma2(flo,p2,A[0][4]); A[0][5]=ffma2(flo,s2,A[0][5]);  \
    A[0][6]=ffma2(flo,p3,A[0][6]); A[0][7]=ffma2(flo,s3,A[0][7]);  \
    A[0][8]=ffma2(flo,p4,A[0][8]);                                  \
    A[1][0]=ffma2(fhi,p1,A[1][0]); A[1][1]=ffma2(fhi,s1,A[1][1]);  \
    A[1][2]=ffma2(fhi,p2,A[1][2]); A[1][3]=ffma2(fhi,s2,A[1][3]);  \
    A[1][4]=ffma2(fhi,p3,A[1][4]); A[1][5]=ffma2(fhi,s3,A[1][5]);  \
    A[1][6]=ffma2(fhi,p4,A[1][6]); A[1][7]=ffma2(fhi,s4,A[1][7]);  \
    A[1][8]=ffma2(fhi,p5,A[1][8]);

#define CORR_STEP(FV, WA, WB, WC)                                              \
    {                                                                          \
        u64 p0 = WA.x, p1 = WA.y, p2 = WB.x, p3 = WB.y, p4 = WC.x, p5 = WC.y; \
        u64 s0 = shp(p0,p1), s1 = shp(p1,p2), s2 = shp(p2,p3),                \
            s3 = shp(p3,p4), s4 = shp(p4,p5);                                 \
        CORR_TAPS(FV.x, FV.y, p0,p1,p2,p3,p4,p5, s0,s1,s2,s3,s4, acc2)        \
    }

#define CORR_MAIN_PIPE(SRC, FP, DO_FSQ)                                        \
    {                                                                          \
        ulonglong2 fvA = *(const ulonglong2*)(SRC);                            \
        const ulonglong2* wrA = (const ulonglong2*)(FP);                       \
        ulonglong2 waA = wrA[0], wbA = wrA[1], wcA = wrA[2];                   \
        _Pragma("unroll 2")                                                    \
        for (int c = 0; c < 63; c++) {                                         \
            ulonglong2 fvB = *(const ulonglong2*)((SRC) + (c+1) * NHW);        \
            const ulonglong2* wrB = (const ulonglong2*)((FP) + (c+1) * FPAD);  \
            ulonglong2 waB = wrB[0], wbB = wrB[1], wcB = wrB[2];               \
            DO_FSQ                                                             \
            CORR_STEP(fvA, waA, wbA, wcA)                                      \
            fvA = fvB; waA = waB; wbA = wbB; wcA = wcB;                        \
        }                                                                      \
        DO_FSQ                                                                 \
        CORR_STEP(fvA, waA, wbA, wcA)                                          \
    }

// ================= K1: corr + residual (pipelined LDG, packed FFMA2) =================
__global__ __launch_bounds__(288, 3) void k_corr_res(const float* __restrict__ flt_in, int use_in) {
    __shared__ float s[8128];
    int tid = threadIdx.x;
    int h = tid / 72;
    int r = tid - h * 72;
    int dy = r >> 3;
    int xg = r & 7;
    int x0 = xg * 4;
    int bx = blockIdx.x;
    int bi = bx >> 5;
    int y0 = bx & 31;

    const float* fltp = (use_in ? flt_in : g_flt) + bi * NCHW + y0 * NW + x0 + h * 64 * NHW;
    const float* fp   = g_featpad + bi * FPAD_C + (y0 + dy) * 40 + x0 + h * 64 * FPAD;

    u64 acc2[2][9];
    #pragma unroll
    for (int i = 0; i < 9; i++) { acc2[0][i] = 0ull; acc2[1][i] = 0ull; }
    u64 fsq2 = 0ull;
    bool do_fsq = (dy == 0);

    CORR_MAIN_PIPE(fltp, fp,
        if (do_fsq) fsq2 = ffma2(fvA.x, fvA.x, ffma2(fvA.y, fvA.y, fsq2));
    )

    if (h > 0) {
        u64* ap = (u64*)s + (h - 1) * 1296 + r * 18;
        #pragma unroll
        for (int i = 0; i < 9; i++) { ap[i] = acc2[0][i]; ap[9 + i] = acc2[1][i]; }
    }
    __syncthreads();

    float srcp = 0.f;
    if (h == 0) {
        #pragma unroll
        for (int hh = 0; hh < 3; hh++) {
            const u64* ap = (const u64*)s + hh * 1296 + r * 18;
            #pragma unroll
            for (int i = 0; i < 9; i++) {
                acc2[0][i] = addf2(acc2[0][i], ap[i]);
                acc2[1][i] = addf2(acc2[1][i], ap[9 + i]);
            }
        }
        #pragma unroll
        for (int dx = 0; dx < 9; dx++) {
            int k = dy * 9 + dx;
            float m  = g_wm[k];
            float lm = g_wlab[k];
            float sw = g_wsw[k];
            float a0 = 0.5f * (1.f - m);
            float a1 = 0.5f * (1.f + m);
            float accs[4] = {lo32(acc2[0][dx]), hi32(acc2[0][dx]),
                             lo32(acc2[1][dx]), hi32(acc2[1][dx])};
            float4 mo, ko;
            float* mp = (float*)&mo; float* kp = (float*)&ko;
            #pragma unroll
            for (int j = 0; j < 4; j++) {
                float sv = accs[j];
                float sact  = a0 * fabsf(sv) + a1 * sv;
                float sgn   = (sv > 0.f) ? 1.f : ((sv < 0.f) ? -1.f : 0.f);
                float smask = a0 * sgn + a1;
                float lres  = sw * (sact - lm);
                srcp += lres * lres;
                mp[j] = smask * sw * lres;
                kp[j] = sw * smask;
            }
            int gi = ((bi * NK + k) * NH + y0) * NW + x0;
            *(float4*)(g_mapped + gi) = mo;
            *(float4*)(g_maskw  + gi) = ko;
        }
        s[7776 + r] = srcp;
    }
    if (do_fsq) s[7848 + h * 8 + xg] = lo32(fsq2) + hi32(fsq2);
    __syncthreads();
    if (tid == 0) {
        float a = 0.f, b = 0.f;
        #pragma unroll
        for (int i = 0; i < 72; i++) a += s[7776 + i];
        #pragma unroll
        for (int i = 0; i < 32; i++) b += s[7848 + i];
        g_psrc[bx] = a;
        g_pfsq[bx] = b;
    }
}

// ================= K2: transpose v3 — 8 ch/thread, 8 rows/block =================
// grid 256 = bi(16) x ygrp(4, 8 rows) x qtr(4, 64ch); 128 thr = cslot(2,8ch) x yl(8) x xg(8)
__global__ __launch_bounds__(128, 5) void k_transpose(const float* __restrict__ flt_in,
                                                      int use_in, int iter) {
    __shared__ float s[10240];   // feat: 16ch x 16 rows x 40 = 10240 floats (40KB)
    int tid = threadIdx.x;
    int bx = blockIdx.x;
    int bi = bx >> 4;
    int rem = bx & 15;
    int y0 = (rem >> 2) * 8;
    int qtr = rem & 3;
    int cslot = tid >> 6;        // 0..1, 8 channels each
    int yl = (tid >> 3) & 7;     // 0..7
    int x0 = (tid & 7) * 4;

    if (bx == 0 && tid < 32) {
        float a = 0.f, b = 0.f;
        #pragma unroll
        for (int i = 0; i < 16; i++) { a += g_psrc[tid + 32*i]; b += g_pfsq[tid + 32*i]; }
        #pragma unroll
        for (int o = 16; o; o >>= 1) {
            a += __shfl_down_sync(0xffffffffu, a, o);
            b += __shfl_down_sync(0xffffffffu, b, o);
        }
        if (tid == 0) {
            g_losses[iter * 2 + 0] = 0.5f * a / (float)NB;
            g_losses[iter * 2 + 1] = 0.5f * g_regw * b / (float)NB;
        }
    }

    const float* fltp = (use_in ? flt_in : g_flt) + bi * NCHW;
    const float* fpb  = g_featpad + bi * FPAD_C;
    const float* rbase = g_mapped + bi * NK * NHW + (y0 + yl) * NW + x0;
    float* fgb = g_fg + bi * NCHW;
    float regw = g_regw;
    float an[4] = {0.f, 0.f, 0.f, 0.f};

    for (int ci = 0; ci < 4; ci++) {
        int cb = qtr * 64 + ci * 16;
        __syncthreads();
        // stage 16 channels x 16 rows x 40 floats = 2560 float4
        for (int t = tid; t < 2560; t += 128) {
            int c = t / 160; int r2 = t - c * 160;
            int ry = r2 / 10; int e = r2 - ry * 10;
            *(float4*)(s + c * 640 + ry * 40 + e * 4) =
                *(const float4*)(fpb + (cb + c) * FPAD + (y0 + ry) * 40 + e * 4);
        }
        __syncthreads();

        int c1 = cslot * 8;
        float a[8][4];
        #pragma unroll
        for (int cc = 0; cc < 8; cc++)
            #pragma unroll
            for (int j = 0; j < 4; j++) a[cc][j] = 0.f;

        for (int dyy = 0; dyy < 9; dyy++) {
            float4 rr[9];
            #pragma unroll
            for (int dx = 0; dx < 9; dx++)
                rr[dx] = *(const float4*)(rbase + (dyy * 9 + dx) * NHW);
            #pragma unroll
            for (int cc = 0; cc < 8; cc++) {
                const float* wp = s + (c1 + cc) * 640 + (yl + dyy) * 40 + x0;
                float4 wa = *(const float4*)wp;
                float4 wb = *(const float4*)(wp + 4);
                float4 wc = *(const float4*)(wp + 8);
                float w[12] = {wa.x,wa.y,wa.z,wa.w, wb.x,wb.y,wb.z,wb.w, wc.x,wc.y,wc.z,wc.w};
                #pragma unroll
                for (int dx = 0; dx < 9; dx++) {
                    a[cc][0] += rr[dx].x * w[dx];
                    a[cc][1] += rr[dx].y * w[dx+1];
                    a[cc][2] += rr[dx].z * w[dx+2];
                    a[cc][3] += rr[dx].w * w[dx+3];
                }
            }
        }
        #pragma unroll
        for (int cc = 0; cc < 8; cc++) {
            int gi = (cb + c1 + cc) * NHW + (y0 + yl) * NW + x0;
            float4 fv = *(const float4*)(fltp + gi);
            float4 o;
            o.x = a[cc][0] + regw * fv.x;
            o.y = a[cc][1] + regw * fv.y;
            o.z = a[cc][2] + regw * fv.z;
            o.w = a[cc][3] + regw * fv.w;
            *(float4*)(fgb + gi) = o;
            an[0] += o.x*o.x; an[1] += o.y*o.y; an[2] += o.z*o.z; an[3] += o.w*o.w;
        }
    }

    __syncthreads();
    // reduce anum across 2 cslots: smem [cslot][yl(8)][32x] = 512 floats
    #pragma unroll
    for (int j = 0; j < 4; j++)
        s[cslot * 256 + yl * 32 + x0 + j] = an[j];
    __syncthreads();
    for (int e = tid; e < 256; e += 128) {
        int yy = e >> 5, x = e & 31;
        float a = s[e] + s[256 + e];
        g_anum[qtr * NBHW + bi * NHW + (y0 + yy) * NW + x] = a;
    }
}

// ================= K3: corr(fg) pipelined -> alpha -> fused update =================
__global__ __launch_bounds__(288, 3) void k_corr_grad(const float* __restrict__ flt_in,
                                                      int use_in, float* __restrict__ out, int last) {
    __shared__ float s[8128];
    int tid = threadIdx.x;
    int h = tid / 72;
    int r = tid - h * 72;
    int dy = r >> 3;
    int xg = r & 7;
    int x0 = xg * 4;
    int bx = blockIdx.x;
    int bi = bx >> 5;
    int y0 = bx & 31;

    const float* fgp = g_fg + bi * NCHW + y0 * NW + x0 + h * 64 * NHW;
    const float* fp  = g_featpad + bi * FPAD_C + (y0 + dy) * 40 + x0 + h * 64 * FPAD;

    u64 acc2[2][9];
    #pragma unroll
    for (int i = 0; i < 9; i++) { acc2[0][i] = 0ull; acc2[1][i] = 0ull; }

    CORR_MAIN_PIPE(fgp, fp, )

    if (h > 0) {
        u64* ap = (u64*)s + (h - 1) * 1296 + r * 18;
        #pragma unroll
        for (int i = 0; i < 9; i++) { ap[i] = acc2[0][i]; ap[9 + i] = acc2[1][i]; }
    }
    __syncthreads();

    if (h == 0) {
        #pragma unroll
        for (int hh = 0; hh < 3; hh++) {
            const u64* ap = (const u64*)s + hh * 1296 + r * 18;
            #pragma unroll
            for (int i = 0; i < 9; i++) {
                acc2[0][i] = addf2(acc2[0][i], ap[i]);
                acc2[1][i] = addf2(acc2[1][i], ap[9 + i]);
            }
        }
        u64 denl2[2] = {0ull, 0ull};
        #pragma unroll
        for (int dx = 0; dx < 9; dx++) {
            int k = dy * 9 + dx;
            int gi = ((bi * NK + k) * NH + y0) * NW + x0;
            ulonglong2 mk = *(const ulonglong2*)(g_maskw + gi);
            u64 t0 = mulf2(mk.x, acc2[0][dx]);
            u64 t1 = mulf2(mk.y, acc2[1][dx]);
            denl2[0] = ffma2(t0, t0, denl2[0]);
            denl2[1] = ffma2(t1, t1, denl2[1]);
        }
        s[7776 + dy * 32 + x0 + 0] = lo32(denl2[0]);
        s[7776 + dy * 32 + x0 + 1] = hi32(denl2[0]);
        s[7776 + dy * 32 + x0 + 2] = lo32(denl2[1]);
        s[7776 + dy * 32 + x0 + 3] = hi32(denl2[1]);
    }
    __syncthreads();

    if (tid < 32) {
        int x = tid;
        float d = 0.f;
        #pragma unroll
        for (int q = 0; q < 9; q++) d += s[7776 + q * 32 + x];
        int pi = bi * NHW + y0 * NW + x;
        float num = g_anum[pi] + g_anum[NBHW + pi] + g_anum[2*NBHW + pi] + g_anum[3*NBHW + pi];
        float ad = fmaxf(d + g_regw * num, 1e-8f);
        s[8064 + x] = num / ad;
    }
    __syncthreads();

    const float* fbase = use_in ? flt_in : g_flt;
    float* dst = last ? out : g_flt;
    float step = g_step;
    for (int t = tid; t < 2048; t += 288) {
        int c = t >> 3; int e = t & 7;
        int gi = bi * NCHW + c * NHW + y0 * NW + e * 4;
        float4 fg4 = *(const float4*)(g_fg + gi);
        float4 fv  = *(const float4*)(fbase + gi);
        float al0 = s[8064 + e * 4 + 0];
        float al1 = s[8064 + e * 4 + 1];
        float al2 = s[8064 + e * 4 + 2];
        float al3 = s[8064 + e * 4 + 3];
        float4 o;
        o.x = fv.x - step * al0 * fg4.x;
        o.y = fv.y - step * al1 * fg4.y;
        o.z = fv.z - step * al2 * fg4.z;
        o.w = fv.w - step * al3 * fg4.w;
        *(float4*)(dst + gi) = o;
    }

    if (last && bx == 0 && tid < 9) {
        float v;
        if (tid < 3)       v = g_losses[tid * 2] + g_losses[tid * 2 + 1];
        else if (tid < 6)  v = g_losses[(tid - 3) * 2];
        else               v = g_losses[(tid - 6) * 2 + 1];
        out[OUT_FLT + tid] = v;
    }
}

extern "C" void kernel_launch(void* const* d_in, const int* in_sizes, int n_in,
                              void* d_out, int out_size) {
    const float* flt  = (const float*)d_in[0];
    const float* feat = (const float*)d_in[1];
    const float* lw   = (const float*)d_in[2];
    const float* mw   = (const float*)d_in[3];
    const float* sw   = (const float*)d_in[4];
    const float* ls   = (const float*)d_in[5];
    const float* fr   = (const float*)d_in[6];
    float* out = (float*)d_out;

    k_prepad<<<4096, 128>>>(feat, lw, mw, sw, ls, fr);
    for (int it = 0; it < 3; it++) {
        int first = (it == 0) ? 1 : 0;
        int last  = (it == 2) ? 1 : 0;
        k_corr_res<<<512, 288>>>(flt, first);
        k_transpose<<<256, 128>>>(flt, first, it);
        k_corr_grad<<<512, 288>>>(flt, first, out, last);
    }
}

// round 17
// speedup vs baseline: 1.0830x; 1.0830x over previous
#include <cuda_runtime.h>
#include <math.h>

#define NB 16
#define NC 256
#define NH 32
#define NW 32
#define NK 81
#define NHW 1024
#define NCHW (NC*NHW)
#define NBHW (NB*NHW)
#define OUT_FLT (NB*NCHW)
#define FPAD 1600              // 40 rows x 40 floats
#define FPAD_C (NC*FPAD)

typedef unsigned long long u64;

__device__ __forceinline__ u64 ffma2(u64 a, u64 b, u64 c) {
    u64 d;
    asm("fma.rn.f32x2 %0, %1, %2, %3;" : "=l"(d) : "l"(a), "l"(b), "l"(c));
    return d;
}
__device__ __forceinline__ u64 addf2(u64 a, u64 b) {
    u64 d;
    asm("add.rn.f32x2 %0, %1, %2;" : "=l"(d) : "l"(a), "l"(b));
    return d;
}
__device__ __forceinline__ u64 mulf2(u64 a, u64 b) {
    u64 d;
    asm("mul.rn.f32x2 %0, %1, %2;" : "=l"(d) : "l"(a), "l"(b));
    return d;
}
__device__ __forceinline__ u64 shp(u64 a, u64 b) {   // (hi(a), lo(b))
    return (a >> 32) | (b << 32);
}
__device__ __forceinline__ float lo32(u64 a) { return __uint_as_float((unsigned)a); }
__device__ __forceinline__ float hi32(u64 a) { return __uint_as_float((unsigned)(a >> 32)); }

// ---------------- device scratch ----------------
__device__ float g_wlab[NK], g_wm[NK], g_wsw[NK];
__device__ float g_step, g_regw;
__device__ float g_flt[NB*NCHW];
__device__ float g_fg[NB*NCHW];
__device__ float g_mapped[NB*NK*NHW];
__device__ float g_maskw[NB*NK*NHW];
__device__ float g_anum[4*NBHW];
__device__ float g_featpad[NB*FPAD_C];   // 26.2 MB
__device__ float g_psrc[512], g_pfsq[512];
__device__ float g_losses[6];

// ---------------- prepad + init (merged) ----------------
__global__ void k_prepad(const float* __restrict__ feat,
                         const float* __restrict__ label_w,
                         const float* __restrict__ mask_w,
                         const float* __restrict__ spatial_w,
                         const float* __restrict__ logstep,
                         const float* __restrict__ freg) {
    if (blockIdx.x == 0) {
        int t = threadIdx.x;
        if (t < NK) {
            int k0 = t / 9, k1 = t % 9;
            float dist = sqrtf((float)((k0-4)*(k0-4) + (k1-4)*(k1-4)));
            float lab = 0.f, mk = 0.f, sw = 0.f;
            #pragma unroll
            for (int d = 0; d < 10; d++) {
                float diff = dist * 2.0f - (float)d;
                float bv;
                if (d < 9) bv = fmaxf(0.f, 1.f - fabsf(diff));
                else       bv = fminf(fmaxf(1.f + diff, 0.f), 1.f);
                lab += bv * label_w[d];
                mk  += bv * mask_w[d];
                sw  += bv * spatial_w[d];
            }
            g_wlab[t] = lab;
            g_wm[t]   = 1.f / (1.f + expf(-mk));
            g_wsw[t]  = sw;
        }
        if (t == 96) g_step = expf(logstep[0]);
        if (t == 97) {
            float fr = freg[0];
            g_regw = fmaxf(fr * fr, 1e-10f) / ((float)NC * (float)NC);
        }
    }
    int bc = blockIdx.x;
    const float* src = feat + bc * NHW;
    float4* dst = (float4*)(g_featpad + bc * FPAD);
    for (int t = threadIdx.x; t < 400; t += 128) {
        int py = t / 10, e = t - py * 10;
        float4 v = make_float4(0.f, 0.f, 0.f, 0.f);
        if (py >= 4 && py < 36 && e >= 1 && e <= 8)
            v = *(const float4*)(src + (py - 4) * NW + e * 4 - 4);
        dst[t] = v;
    }
}

#define CORR_TAPS(flo, fhi, p0,p1,p2,p3,p4,p5, s0,s1,s2,s3,s4, A)  \
    A[0][0]=ffma2(flo,p0,A[0][0]); A[0][1]=ffma2(flo,s0,A[0][1]);  \
    A[0][2]=ffma2(flo,p1,A[0][2]); A[0][3]=ffma2(flo,s1,A[0][3]);  \
    A[0][4]=ffma2(flo,p2,A[0][4]); A[0][5]=ffma2(flo,s2,A[0][5]);  \
    A[0][6]=ffma2(flo,p3,A[0][6]); A[0][7]=ffma2(flo,s3,A[0][7]);  \
    A[0][8]=ffma2(flo,p4,A[0][8]);                                  \
    A[1][0]=ffma2(fhi,p1,A[1][0]); A[1][1]=ffma2(fhi,s1,A[1][1]);  \
    A[1][2]=ffma2(fhi,p2,A[1][2]); A[1][3]=ffma2(fhi,s2,A[1][3]);  \
    A[1][4]=ffma2(fhi,p3,A[1][4]); A[1][5]=ffma2(fhi,s3,A[1][5]);  \
    A[1][6]=ffma2(fhi,p4,A[1][6]); A[1][7]=ffma2(fhi,s4,A[1][7]);  \
    A[1][8]=ffma2(fhi,p5,A[1][8]);

#define CORR_STEP(FV, WA, WB, WC)                                              \
    {                                                                          \
        u64 p0 = WA.x, p1 = WA.y, p2 = WB.x, p3 = WB.y, p4 = WC.x, p5 = WC.y; \
        u64 s0 = shp(p0,p1), s1 = shp(p1,p2), s2 = shp(p2,p3),                \
            s3 = shp(p3,p4), s4 = shp(p4,p5);                                 \
        CORR_TAPS(FV.x, FV.y, p0,p1,p2,p3,p4,p5, s0,s1,s2,s3,s4, acc2)        \
    }

#define CORR_MAIN_PIPE(SRC, FP, DO_FSQ)                                        \
    {                                                                          \
        ulonglong2 fvA = *(const ulonglong2*)(SRC);                            \
        const ulonglong2* wrA = (const ulonglong2*)(FP);                       \
        ulonglong2 waA = wrA[0], wbA = wrA[1], wcA = wrA[2];                   \
        _Pragma("unroll 2")                                                    \
        for (int c = 0; c < 63; c++) {                                         \
            ulonglong2 fvB = *(const ulonglong2*)((SRC) + (c+1) * NHW);        \
            const ulonglong2* wrB = (const ulonglong2*)((FP) + (c+1) * FPAD);  \
            ulonglong2 waB = wrB[0], wbB = wrB[1], wcB = wrB[2];               \
            DO_FSQ                                                             \
            CORR_STEP(fvA, waA, wbA, wcA)                                      \
            fvA = fvB; waA = waB; wbA = wbB; wcA = wcB;                        \
        }                                                                      \
        DO_FSQ                                                                 \
        CORR_STEP(fvA, waA, wbA, wcA)                                          \
    }

// ================= K1: corr + residual (pipelined LDG, packed FFMA2) =================
__global__ __launch_bounds__(288, 3) void k_corr_res(const float* __restrict__ flt_in, int use_in) {
    __shared__ float s[8128];
    int tid = threadIdx.x;
    int h = tid / 72;
    int r = tid - h * 72;
    int dy = r >> 3;
    int xg = r & 7;
    int x0 = xg * 4;
    int bx = blockIdx.x;
    int bi = bx >> 5;
    int y0 = bx & 31;

    const float* fltp = (use_in ? flt_in : g_flt) + bi * NCHW + y0 * NW + x0 + h * 64 * NHW;
    const float* fp   = g_featpad + bi * FPAD_C + (y0 + dy) * 40 + x0 + h * 64 * FPAD;

    u64 acc2[2][9];
    #pragma unroll
    for (int i = 0; i < 9; i++) { acc2[0][i] = 0ull; acc2[1][i] = 0ull; }
    u64 fsq2 = 0ull;
    bool do_fsq = (dy == 0);

    CORR_MAIN_PIPE(fltp, fp,
        if (do_fsq) fsq2 = ffma2(fvA.x, fvA.x, ffma2(fvA.y, fvA.y, fsq2));
    )

    if (h > 0) {
        u64* ap = (u64*)s + (h - 1) * 1296 + r * 18;
        #pragma unroll
        for (int i = 0; i < 9; i++) { ap[i] = acc2[0][i]; ap[9 + i] = acc2[1][i]; }
    }
    __syncthreads();

    float srcp = 0.f;
    if (h == 0) {
        #pragma unroll
        for (int hh = 0; hh < 3; hh++) {
            const u64* ap = (const u64*)s + hh * 1296 + r * 18;
            #pragma unroll
            for (int i = 0; i < 9; i++) {
                acc2[0][i] = addf2(acc2[0][i], ap[i]);
                acc2[1][i] = addf2(acc2[1][i], ap[9 + i]);
            }
        }
        #pragma unroll
        for (int dx = 0; dx < 9; dx++) {
            int k = dy * 9 + dx;
            float m  = g_wm[k];
            float lm = g_wlab[k];
            float sw = g_wsw[k];
            float a0 = 0.5f * (1.f - m);
            float a1 = 0.5f * (1.f + m);
            float accs[4] = {lo32(acc2[0][dx]), hi32(acc2[0][dx]),
                             lo32(acc2[1][dx]), hi32(acc2[1][dx])};
            float4 mo, ko;
            float* mp = (float*)&mo; float* kp = (float*)&ko;
            #pragma unroll
            for (int j = 0; j < 4; j++) {
                float sv = accs[j];
                float sact  = a0 * fabsf(sv) + a1 * sv;
                float sgn   = (sv > 0.f) ? 1.f : ((sv < 0.f) ? -1.f : 0.f);
                float smask = a0 * sgn + a1;
                float lres  = sw * (sact - lm);
                srcp += lres * lres;
                mp[j] = smask * sw * lres;
                kp[j] = sw * smask;
            }
            int gi = ((bi * NK + k) * NH + y0) * NW + x0;
            *(float4*)(g_mapped + gi) = mo;
            *(float4*)(g_maskw  + gi) = ko;
        }
        s[7776 + r] = srcp;
    }
    if (do_fsq) s[7848 + h * 8 + xg] = lo32(fsq2) + hi32(fsq2);
    __syncthreads();
    if (tid == 0) {
        float a = 0.f, b = 0.f;
        #pragma unroll
        for (int i = 0; i < 72; i++) a += s[7776 + i];
        #pragma unroll
        for (int i = 0; i < 32; i++) b += s[7848 + i];
        g_psrc[bx] = a;
        g_pfsq[bx] = b;
    }
}

// ================= K2: transpose v2 — 4 ch/thread, 4 rows/block =================
// grid 512 = bi(16) x ygrp(8, 4 rows) x qtr(4, 64ch); 128 thr = cslot(4,4ch) x yl(4) x xg(8)
__global__ __launch_bounds__(128, 6) void k_transpose(const float* __restrict__ flt_in,
                                                      int use_in, int iter) {
    __shared__ float s[7680];   // feat: 16ch x 12 rows x 40 = 7680 floats (30.7KB)
    int tid = threadIdx.x;
    int bx = blockIdx.x;
    int bi = bx >> 5;
    int rem = bx & 31;
    int y0 = (rem >> 2) * 4;
    int qtr = rem & 3;
    int cslot = tid >> 5;        // 0..3, 4 channels each
    int yl = (tid >> 3) & 3;     // 0..3
    int x0 = (tid & 7) * 4;

    if (bx == 0 && tid < 32) {
        float a = 0.f, b = 0.f;
        #pragma unroll
        for (int i = 0; i < 16; i++) { a += g_psrc[tid + 32*i]; b += g_pfsq[tid + 32*i]; }
        #pragma unroll
        for (int o = 16; o; o >>= 1) {
            a += __shfl_down_sync(0xffffffffu, a, o);
            b += __shfl_down_sync(0xffffffffu, b, o);
        }
        if (tid == 0) {
            g_losses[iter * 2 + 0] = 0.5f * a / (float)NB;
            g_losses[iter * 2 + 1] = 0.5f * g_regw * b / (float)NB;
        }
    }

    const float* fltp = (use_in ? flt_in : g_flt) + bi * NCHW;
    const float* fpb  = g_featpad + bi * FPAD_C;
    const float* rbase = g_mapped + bi * NK * NHW + (y0 + yl) * NW + x0;
    float* fgb = g_fg + bi * NCHW;
    float regw = g_regw;
    float an[4] = {0.f, 0.f, 0.f, 0.f};

    for (int ci = 0; ci < 4; ci++) {
        int cb = qtr * 64 + ci * 16;
        __syncthreads();
        // stage 16 channels x 12 rows x 40 floats = 1920 float4
        for (int t = tid; t < 1920; t += 128) {
            int c = t / 120; int r2 = t - c * 120;
            int ry = r2 / 10; int e = r2 - ry * 10;
            *(float4*)(s + c * 480 + ry * 40 + e * 4) =
                *(const float4*)(fpb + (cb + c) * FPAD + (y0 + ry) * 40 + e * 4);
        }
        __syncthreads();

        int c1 = cslot * 4;
        float a[4][4] = {{0.f,0.f,0.f,0.f},{0.f,0.f,0.f,0.f},
                         {0.f,0.f,0.f,0.f},{0.f,0.f,0.f,0.f}};
        for (int dyy = 0; dyy < 9; dyy++) {
            float4 rr[9];
            #pragma unroll
            for (int dx = 0; dx < 9; dx++)
                rr[dx] = *(const float4*)(rbase + (dyy * 9 + dx) * NHW);
            #pragma unroll
            for (int cc = 0; cc < 4; cc++) {
                const float* wp = s + (c1 + cc) * 480 + (yl + dyy) * 40 + x0;
                float4 wa = *(const float4*)wp;
                float4 wb = *(const float4*)(wp + 4);
                float4 wc = *(const float4*)(wp + 8);
                float w[12] = {wa.x,wa.y,wa.z,wa.w, wb.x,wb.y,wb.z,wb.w, wc.x,wc.y,wc.z,wc.w};
                #pragma unroll
                for (int dx = 0; dx < 9; dx++) {
                    a[cc][0] += rr[dx].x * w[dx];
                    a[cc][1] += rr[dx].y * w[dx+1];
                    a[cc][2] += rr[dx].z * w[dx+2];
                    a[cc][3] += rr[dx].w * w[dx+3];
                }
            }
        }
        #pragma unroll
        for (int cc = 0; cc < 4; cc++) {
            int gi = (cb + c1 + cc) * NHW + (y0 + yl) * NW + x0;
            float4 fv = *(const float4*)(fltp + gi);
            float4 o;
            o.x = a[cc][0] + regw * fv.x;
            o.y = a[cc][1] + regw * fv.y;
            o.z = a[cc][2] + regw * fv.z;
            o.w = a[cc][3] + regw * fv.w;
            *(float4*)(fgb + gi) = o;
            an[0] += o.x*o.x; an[1] += o.y*o.y; an[2] += o.z*o.z; an[3] += o.w*o.w;
        }
    }

    __syncthreads();
    // reduce anum across 4 cslots: smem [cslot][yl][32x]
    #pragma unroll
    for (int j = 0; j < 4; j++)
        s[cslot * 128 + yl * 32 + x0 + j] = an[j];
    __syncthreads();
    if (tid < 128) {
        int yy = tid >> 5, x = tid & 31;
        float a = s[yy * 32 + x] + s[128 + yy * 32 + x] + s[256 + yy * 32 + x] + s[384 + yy * 32 + x];
        g_anum[qtr * NBHW + bi * NHW + (y0 + yy) * NW + x] = a;
    }
}

// ================= K3: corr(fg) pipelined -> alpha -> fused update =================
__global__ __launch_bounds__(288, 3) void k_corr_grad(const float* __restrict__ flt_in,
                                                      int use_in, float* __restrict__ out, int last) {
    __shared__ float s[8128];
    int tid = threadIdx.x;
    int h = tid / 72;
    int r = tid - h * 72;
    int dy = r >> 3;
    int xg = r & 7;
    int x0 = xg * 4;
    int bx = blockIdx.x;
    int bi = bx >> 5;
    int y0 = bx & 31;

    const float* fgp = g_fg + bi * NCHW + y0 * NW + x0 + h * 64 * NHW;
    const float* fp  = g_featpad + bi * FPAD_C + (y0 + dy) * 40 + x0 + h * 64 * FPAD;

    u64 acc2[2][9];
    #pragma unroll
    for (int i = 0; i < 9; i++) { acc2[0][i] = 0ull; acc2[1][i] = 0ull; }

    CORR_MAIN_PIPE(fgp, fp, )

    if (h > 0) {
        u64* ap = (u64*)s + (h - 1) * 1296 + r * 18;
        #pragma unroll
        for (int i = 0; i < 9; i++) { ap[i] = acc2[0][i]; ap[9 + i] = acc2[1][i]; }
    }
    __syncthreads();

    if (h == 0) {
        #pragma unroll
        for (int hh = 0; hh < 3; hh++) {
            const u64* ap = (const u64*)s + hh * 1296 + r * 18;
            #pragma unroll
            for (int i = 0; i < 9; i++) {
                acc2[0][i] = addf2(acc2[0][i], ap[i]);
                acc2[1][i] = addf2(acc2[1][i], ap[9 + i]);
            }
        }
        u64 denl2[2] = {0ull, 0ull};
        #pragma unroll
        for (int dx = 0; dx < 9; dx++) {
            int k = dy * 9 + dx;
            int gi = ((bi * NK + k) * NH + y0) * NW + x0;
            ulonglong2 mk = *(const ulonglong2*)(g_maskw + gi);
            u64 t0 = mulf2(mk.x, acc2[0][dx]);
            u64 t1 = mulf2(mk.y, acc2[1][dx]);
            denl2[0] = ffma2(t0, t0, denl2[0]);
            denl2[1] = ffma2(t1, t1, denl2[1]);
        }
        s[7776 + dy * 32 + x0 + 0] = lo32(denl2[0]);
        s[7776 + dy * 32 + x0 + 1] = hi32(denl2[0]);
        s[7776 + dy * 32 + x0 + 2] = lo32(denl2[1]);
        s[7776 + dy * 32 + x0 + 3] = hi32(denl2[1]);
    }
    __syncthreads();

    if (tid < 32) {
        int x = tid;
        float d = 0.f;
        #pragma unroll
        for (int q = 0; q < 9; q++) d += s[7776 + q * 32 + x];
        int pi = bi * NHW + y0 * NW + x;
        float num = g_anum[pi] + g_anum[NBHW + pi] + g_anum[2*NBHW + pi] + g_anum[3*NBHW + pi];
        float ad = fmaxf(d + g_regw * num, 1e-8f);
        s[8064 + x] = num / ad;
    }
    __syncthreads();

    const float* fbase = use_in ? flt_in : g_flt;
    float* dst = last ? out : g_flt;
    float step = g_step;
    for (int t = tid; t < 2048; t += 288) {
        int c = t >> 3; int e = t & 7;
        int gi = bi * NCHW + c * NHW + y0 * NW + e * 4;
        float4 fg4 = *(const float4*)(g_fg + gi);
        float4 fv  = *(const float4*)(fbase + gi);
        float al0 = s[8064 + e * 4 + 0];
        float al1 = s[8064 + e * 4 + 1];
        float al2 = s[8064 + e * 4 + 2];
        float al3 = s[8064 + e * 4 + 3];
        float4 o;
        o.x = fv.x - step * al0 * fg4.x;
        o.y = fv.y - step * al1 * fg4.y;
        o.z = fv.z - step * al2 * fg4.z;
        o.w = fv.w - step * al3 * fg4.w;
        *(float4*)(dst + gi) = o;
    }

    if (last && bx == 0 && tid < 9) {
        float v;
        if (tid < 3)       v = g_losses[tid * 2] + g_losses[tid * 2 + 1];
        else if (tid < 6)  v = g_losses[(tid - 3) * 2];
        else               v = g_losses[(tid - 6) * 2 + 1];
        out[OUT_FLT + tid] = v;
    }
}

extern "C" void kernel_launch(void* const* d_in, const int* in_sizes, int n_in,
                              void* d_out, int out_size) {
    const float* flt  = (const float*)d_in[0];
    const float* feat = (const float*)d_in[1];
    const float* lw   = (const float*)d_in[2];
    const float* mw   = (const float*)d_in[3];
    const float* sw   = (const float*)d_in[4];
    const float* ls   = (const float*)d_in[5];
    const float* fr   = (const float*)d_in[6];
    float* out = (float*)d_out;

    k_prepad<<<4096, 128>>>(feat, lw, mw, sw, ls, fr);
    for (int it = 0; it < 3; it++) {
        int first = (it == 0) ? 1 : 0;
        int last  = (it == 2) ? 1 : 0;
        k_corr_res<<<512, 288>>>(flt, first);
        k_transpose<<<512, 128>>>(flt, first, it);
        k_corr_grad<<<512, 288>>>(flt, first, out, last);
    }
}